// round 6
// baseline (speedup 1.0000x reference)
#include <cuda_runtime.h>
#include <math.h>

#define Bn 16
#define Sn 1024
#define En 1024
#define Wn 7
#define HW 3
// ulonglong2 units (16 B = 4 floats):
#define ROW_U2 256               // one (b,row) x-row = 1024 floats = 256 u2
#define VROW_U2 1792             // one (t,v) weight row = 7168 floats = 1792 u2
#define TAP_U2 256               // one tap slice of a v-row
#define WT_U2 (Wn * VROW_U2)     // 12544 u2 per t
#define SMEM_BYTES (2 * Wn * TAP_U2 * 16)   // 57344: double-buffered tap slice

__device__ __forceinline__ void ffma2(unsigned long long& d,
                                      unsigned long long a,
                                      unsigned long long b) {
    asm("fma.rn.f32x2 %0, %1, %2, %0;" : "+l"(d) : "l"(a), "l"(b));
}
__device__ __forceinline__ float2 unpack2(unsigned long long v) {
    float2 r;
    asm("mov.b64 {%0, %1}, %2;" : "=f"(r.x), "=f"(r.y) : "l"(v));
    return r;
}
__device__ __forceinline__ unsigned long long pack2(float a, float b) {
    unsigned long long r;
    asm("mov.b64 %0, {%1, %2};" : "=l"(r) : "f"(a), "f"(b));
    return r;
}
__device__ __forceinline__ float fast_tanh(float v) {
    float r;
    asm("tanh.approx.f32 %0, %1;" : "=f"(r) : "f"(v));
    return r;
}
__device__ __forceinline__ void cp16(unsigned smem_addr, const void* gptr) {
    asm volatile("cp.async.cg.shared.global [%0], [%1], 16;" :: "r"(smem_addr), "l"(gptr));
}
#define CP_COMMIT() asm volatile("cp.async.commit_group;")
#define CP_WAIT0()  asm volatile("cp.async.wait_group 0;")

// One block per timestep t. 256 threads = 8 warps.
// Warp w: bg = w&3 (batches 4bg..4bg+3), kh = w>>2 (E-half).
// Stage 1: logits via smem-staged weight (cp.async double buffer).
// Stage 2: sigmoid. Stage 3: gated 7-tap blend + tanh.
__global__ __launch_bounds__(256, 3)
void soft_reordering_fused(const float* __restrict__ x,
                           const float* __restrict__ weight,
                           const float* __restrict__ bias,
                           float* __restrict__ out)
{
    extern __shared__ char smem_raw[];
    ulonglong2* s_w = (ulonglong2*)smem_raw;           // [2][Wn*TAP_U2]
    __shared__ float s_part[2][Bn][Wn];
    __shared__ float s_g[Bn][8];

    const int t    = blockIdx.x;
    const int tid  = threadIdx.x;
    const int warp = tid >> 5;
    const int lane = tid & 31;
    const int bg   = warp & 3;
    const int kh   = warp >> 2;

    const ulonglong2* x2 = (const ulonglong2*)x;
    const ulonglong2* wt = (const ulonglong2*)weight + (size_t)t * WT_U2;
    const unsigned s_w_base = (unsigned)__cvta_generic_to_shared(s_w);

    unsigned long long acc[4][Wn];
    #pragma unroll
    for (int j = 0; j < 4; j++)
        #pragma unroll
        for (int v = 0; v < Wn; v++) acc[j][v] = 0ULL;

    // Prologue: stage tap 0 into buffer 0.
    #pragma unroll
    for (int j = 0; j < 7; j++) {
        const int flat = tid + j * 256;                // [0, 1792)
        const int v = flat >> 8, e16 = flat & 255;
        cp16(s_w_base + flat * 16, wt + (size_t)v * VROW_U2 + e16);
    }
    CP_COMMIT();

    #pragma unroll 1
    for (int tap = 0; tap < Wn; tap++) {
        CP_WAIT0();          // this tap's buffer filled (my part)
        __syncthreads();     // all parts visible + prev-tap smem reads retired

        // Kick off next tap into the other buffer.
        if (tap < Wn - 1) {
            const int nbuf = (tap + 1) & 1;
            #pragma unroll
            for (int j = 0; j < 7; j++) {
                const int flat = tid + j * 256;
                const int v = flat >> 8, e16 = flat & 255;
                cp16(s_w_base + (nbuf * (Wn * TAP_U2) + flat) * 16,
                     wt + (size_t)v * VROW_U2 + (tap + 1) * TAP_U2 + e16);
            }
            CP_COMMIT();
        }

        const int row = t + tap - HW;
        if (row >= 0 && row < Sn) {
            const int buf_off = (tap & 1) * (Wn * TAP_U2);
            #pragma unroll 2
            for (int i = 0; i < 4; i++) {
                const int q = kh * 128 + i * 32 + lane;    // [0, 256)
                ulonglong2 xv[4];
                #pragma unroll
                for (int j = 0; j < 4; j++)
                    xv[j] = x2[((size_t)(bg * 4 + j) * Sn + row) * ROW_U2 + q];
                #pragma unroll
                for (int v = 0; v < Wn; v++) {
                    const ulonglong2 w2 = s_w[buf_off + v * TAP_U2 + q];
                    #pragma unroll
                    for (int j = 0; j < 4; j++) {
                        ffma2(acc[j][v], xv[j].x, w2.x);
                        ffma2(acc[j][v], xv[j].y, w2.y);
                    }
                }
            }
        }
    }

    // Reduce: unpack pair, warp tree, publish per k-half.
    #pragma unroll
    for (int j = 0; j < 4; j++) {
        #pragma unroll
        for (int v = 0; v < Wn; v++) {
            const float2 p = unpack2(acc[j][v]);
            float s = p.x + p.y;
            s += __shfl_xor_sync(0xffffffffu, s, 16);
            s += __shfl_xor_sync(0xffffffffu, s, 8);
            s += __shfl_xor_sync(0xffffffffu, s, 4);
            s += __shfl_xor_sync(0xffffffffu, s, 2);
            s += __shfl_xor_sync(0xffffffffu, s, 1);
            if (lane == 0) s_part[kh][bg * 4 + j][v] = s;
        }
    }
    __syncthreads();

    if (tid < Bn * Wn) {
        const int b = tid / Wn, v = tid % Wn;
        const float l = s_part[0][b][v] + s_part[1][b][v] + bias[t * Wn + v];
        s_g[b][v] = 1.0f / (1.0f + __expf(-l));
    }
    __syncthreads();

    // Stage 3: out[b,t,:] = tanh(sum_tap g[b][tap] * x[b, t+tap-3, :])
    // Thread owns one 16B column (ROW_U2 == 256 == blockDim).
    const int q = tid;
    #pragma unroll 2
    for (int b = 0; b < Bn; b++) {
        unsigned long long oA = 0ULL, oB = 0ULL;
        #pragma unroll
        for (int tap = 0; tap < Wn; tap++) {
            const int row = t + tap - HW;
            if (row >= 0 && row < Sn) {
                const unsigned long long g2 = pack2(s_g[b][tap], s_g[b][tap]);
                const ulonglong2 xv = x2[((size_t)b * Sn + row) * ROW_U2 + q];
                ffma2(oA, g2, xv.x);
                ffma2(oB, g2, xv.y);
            }
        }
        const float2 a = unpack2(oA), c = unpack2(oB);
        float4 r;
        r.x = fast_tanh(a.x);
        r.y = fast_tanh(a.y);
        r.z = fast_tanh(c.x);
        r.w = fast_tanh(c.y);
        ((float4*)out)[((size_t)b * Sn + t) * ROW_U2 + q] = r;
    }
}

extern "C" void kernel_launch(void* const* d_in, const int* in_sizes, int n_in,
                              void* d_out, int out_size)
{
    const float* x      = (const float*)d_in[0];
    const float* weight = (const float*)d_in[1];
    const float* bias   = (const float*)d_in[2];
    float* out          = (float*)d_out;

    cudaFuncSetAttribute(soft_reordering_fused,
                         cudaFuncAttributeMaxDynamicSharedMemorySize, SMEM_BYTES);
    soft_reordering_fused<<<Sn, 256, SMEM_BYTES>>>(x, weight, bias, out);
}

// round 7
// speedup vs baseline: 1.5753x; 1.5753x over previous
#include <cuda_runtime.h>
#include <math.h>

#define Bn 16
#define Sn 1024
#define En 1024
#define En4 (En / 4)          // 256 float4 per x row
#define Wn 7
#define HW 3
#define VROW4 1792            // one (t,v) weight row = 7168 floats = 1792 float4
#define TAP4 256              // one tap slice of a v-row (float4)
#define WT4 (Wn * VROW4)      // 12544 float4 per t
#define SMEM_BYTES (2 * Wn * TAP4 * 16)   // 57344: double-buffered tap slice

__device__ __forceinline__ float fast_tanh(float v) {
    float r;
    asm("tanh.approx.f32 %0, %1;" : "=f"(r) : "f"(v));
    return r;
}
__device__ __forceinline__ void cp16(unsigned smem_addr, const void* gptr) {
    asm volatile("cp.async.cg.shared.global [%0], [%1], 16;" :: "r"(smem_addr), "l"(gptr));
}
#define CP_COMMIT() asm volatile("cp.async.commit_group;")
#define CP_WAIT0()  asm volatile("cp.async.wait_group 0;")

// One block per timestep t. 256 threads = 8 warps.
// Warp w: bg = w&3 (batches 4bg..4bg+3), kh = w>>2 (E-half).
// Stage 1: logits via smem-staged weight (cp.async double buffer), float4 FMA.
// Stage 2: sigmoid. Stage 3: gated 7-tap blend + tanh.
__global__ __launch_bounds__(256, 3)
void soft_reordering_fused(const float* __restrict__ x,
                           const float* __restrict__ weight,
                           const float* __restrict__ bias,
                           float* __restrict__ out)
{
    extern __shared__ char smem_raw[];
    float4* s_w = (float4*)smem_raw;                   // [2][Wn*TAP4]
    __shared__ float s_part[2][Bn][Wn];
    __shared__ float s_g[Bn][8];

    const int t    = blockIdx.x;
    const int tid  = threadIdx.x;
    const int warp = tid >> 5;
    const int lane = tid & 31;
    const int bg   = warp & 3;
    const int kh   = warp >> 2;

    const float4* x4 = (const float4*)x;
    const float4* wt = (const float4*)weight + (size_t)t * WT4;
    const unsigned s_w_base = (unsigned)__cvta_generic_to_shared(s_w);

    float acc[4][Wn];
    #pragma unroll
    for (int j = 0; j < 4; j++)
        #pragma unroll
        for (int v = 0; v < Wn; v++) acc[j][v] = 0.0f;

    // Prologue: stage tap 0 into buffer 0.
    #pragma unroll
    for (int j = 0; j < 7; j++) {
        const int flat = tid + j * 256;                // [0, 1792)
        const int v = flat >> 8, e4 = flat & 255;
        cp16(s_w_base + flat * 16, wt + (size_t)v * VROW4 + e4);
    }
    CP_COMMIT();

    #pragma unroll 1
    for (int tap = 0; tap < Wn; tap++) {
        CP_WAIT0();          // this tap's buffer filled (my part)
        __syncthreads();     // all parts visible + prev-tap smem reads retired

        // Kick off next tap into the other buffer.
        if (tap < Wn - 1) {
            const int nbuf = (tap + 1) & 1;
            #pragma unroll
            for (int j = 0; j < 7; j++) {
                const int flat = tid + j * 256;
                const int v = flat >> 8, e4 = flat & 255;
                cp16(s_w_base + (nbuf * (Wn * TAP4) + flat) * 16,
                     wt + (size_t)v * VROW4 + (tap + 1) * TAP4 + e4);
            }
            CP_COMMIT();
        }

        const int row = t + tap - HW;
        if (row >= 0 && row < Sn) {
            const int buf_off = (tap & 1) * (Wn * TAP4);
            #pragma unroll 2
            for (int i = 0; i < 4; i++) {
                const int q = kh * 128 + i * 32 + lane;    // [0, 256)
                float4 xv[4];
                #pragma unroll
                for (int j = 0; j < 4; j++)
                    xv[j] = x4[((size_t)(bg * 4 + j) * Sn + row) * En4 + q];
                #pragma unroll
                for (int v = 0; v < Wn; v++) {
                    const float4 w4 = s_w[buf_off + v * TAP4 + q];
                    #pragma unroll
                    for (int j = 0; j < 4; j++) {
                        acc[j][v] = fmaf(xv[j].x, w4.x, acc[j][v]);
                        acc[j][v] = fmaf(xv[j].y, w4.y, acc[j][v]);
                        acc[j][v] = fmaf(xv[j].z, w4.z, acc[j][v]);
                        acc[j][v] = fmaf(xv[j].w, w4.w, acc[j][v]);
                    }
                }
            }
        }
    }

    // Warp tree-reduce 28 partials, publish per k-half.
    #pragma unroll
    for (int j = 0; j < 4; j++) {
        #pragma unroll
        for (int v = 0; v < Wn; v++) {
            float s = acc[j][v];
            s += __shfl_xor_sync(0xffffffffu, s, 16);
            s += __shfl_xor_sync(0xffffffffu, s, 8);
            s += __shfl_xor_sync(0xffffffffu, s, 4);
            s += __shfl_xor_sync(0xffffffffu, s, 2);
            s += __shfl_xor_sync(0xffffffffu, s, 1);
            if (lane == 0) s_part[kh][bg * 4 + j][v] = s;
        }
    }
    __syncthreads();

    if (tid < Bn * Wn) {
        const int b = tid / Wn, v = tid % Wn;
        const float l = s_part[0][b][v] + s_part[1][b][v] + bias[t * Wn + v];
        s_g[b][v] = 1.0f / (1.0f + __expf(-l));
    }
    __syncthreads();

    // Stage 3: out[b,t,:] = tanh(sum_tap g[b][tap] * x[b, t+tap-3, :])
    // Thread owns one 16B column (En4 == 256 == blockDim).
    const int q = tid;
    #pragma unroll 2
    for (int b = 0; b < Bn; b++) {
        float o0 = 0.f, o1 = 0.f, o2 = 0.f, o3 = 0.f;
        #pragma unroll
        for (int tap = 0; tap < Wn; tap++) {
            const int row = t + tap - HW;
            if (row >= 0 && row < Sn) {
                const float g = s_g[b][tap];
                const float4 xv = x4[((size_t)b * Sn + row) * En4 + q];
                o0 = fmaf(g, xv.x, o0);
                o1 = fmaf(g, xv.y, o1);
                o2 = fmaf(g, xv.z, o2);
                o3 = fmaf(g, xv.w, o3);
            }
        }
        float4 r;
        r.x = fast_tanh(o0);
        r.y = fast_tanh(o1);
        r.z = fast_tanh(o2);
        r.w = fast_tanh(o3);
        ((float4*)out)[((size_t)b * Sn + t) * En4 + q] = r;
    }
}

extern "C" void kernel_launch(void* const* d_in, const int* in_sizes, int n_in,
                              void* d_out, int out_size)
{
    const float* x      = (const float*)d_in[0];
    const float* weight = (const float*)d_in[1];
    const float* bias   = (const float*)d_in[2];
    float* out          = (float*)d_out;

    cudaFuncSetAttribute(soft_reordering_fused,
                         cudaFuncAttributeMaxDynamicSharedMemorySize, SMEM_BYTES);
    soft_reordering_fused<<<Sn, 256, SMEM_BYTES>>>(x, weight, bias, out);
}

// round 8
// speedup vs baseline: 1.7301x; 1.0983x over previous
#include <cuda_runtime.h>
#include <math.h>

#define Bn 16
#define Sn 1024
#define En 1024
#define En4 (En / 4)          // 256 float4 per x row
#define Wn 7
#define HW 3
#define VROW4 1792            // one (t,v) weight row = 7168 floats = 1792 float4
#define TAP4 256              // one tap slice of a v-row (float4)
#define WT4 (Wn * VROW4)      // 12544 float4 per t
#define NST 14                // pipeline stages: 7 taps x 2 E-halves
#define STAGE4 896            // float4 per stage slice: 7 v x 128
#define SMEM_BYTES (3 * STAGE4 * 16)   // 43008: 3-deep ring of half-tap slices

__device__ __forceinline__ float fast_tanh(float v) {
    float r;
    asm("tanh.approx.f32 %0, %1;" : "=f"(r) : "f"(v));
    return r;
}
__device__ __forceinline__ void cp16(unsigned smem_addr, const void* gptr) {
    asm volatile("cp.async.cg.shared.global [%0], [%1], 16;" :: "r"(smem_addr), "l"(gptr));
}
#define CP_COMMIT() asm volatile("cp.async.commit_group;")
#define CP_WAIT1()  asm volatile("cp.async.wait_group 1;")

// One block per timestep t. 256 threads = 8 warps.
// Warp w: bg = w&3 (batches 4bg..4bg+3), qh = w>>2 (64-q quarter within each staged half).
// Stage 1: logits via 3-deep cp.async ring of half-tap weight slices.
// Stage 2: sigmoid. Stage 3: gated 7-tap blend + tanh.
__global__ __launch_bounds__(256, 4)
void soft_reordering_fused(const float* __restrict__ x,
                           const float* __restrict__ weight,
                           const float* __restrict__ bias,
                           float* __restrict__ out)
{
    extern __shared__ char smem_raw[];
    float4* s_w = (float4*)smem_raw;                   // [3][STAGE4]
    __shared__ float s_part[2][Bn][Wn];
    __shared__ float s_g[Bn][8];

    const int t    = blockIdx.x;
    const int tid  = threadIdx.x;
    const int warp = tid >> 5;
    const int lane = tid & 31;
    const int bg   = warp & 3;
    const int qh   = warp >> 2;

    const float4* x4 = (const float4*)x;
    const float4* wt = (const float4*)weight + (size_t)t * WT4;
    const unsigned s_w_base = (unsigned)__cvta_generic_to_shared(s_w);

    float acc[4][Wn];
    #pragma unroll
    for (int j = 0; j < 4; j++)
        #pragma unroll
        for (int v = 0; v < Wn; v++) acc[j][v] = 0.0f;

    // Stage slice st (= tap*2 + half) into ring buffer buf.
    // 896 float4 per stage; 256 threads -> 4 chunks, last quarter-guarded.
    #define STAGE_LOAD(st, buf)                                              \
        do {                                                                 \
            const int _tap = (st) >> 1, _half = (st) & 1;                    \
            _Pragma("unroll")                                                \
            for (int _j = 0; _j < 4; _j++) {                                 \
                const int _c = tid + _j * 256;                               \
                if (_c < STAGE4) {                                           \
                    const int _v = _c >> 7, _e4 = _c & 127;                  \
                    cp16(s_w_base + ((buf) * STAGE4 + _c) * 16,              \
                         wt + (size_t)_v * VROW4 + _tap * TAP4               \
                            + _half * 128 + _e4);                            \
                }                                                            \
            }                                                                \
        } while (0)

    STAGE_LOAD(0, 0); CP_COMMIT();
    STAGE_LOAD(1, 1); CP_COMMIT();

    #pragma unroll 1
    for (int st = 0; st < NST; st++) {
        CP_WAIT1();          // everything up to stage st complete (my part)
        __syncthreads();     // all threads' copies visible + buf reuse safe

        // Keep exactly one commit per iteration (uniform group accounting).
        if (st + 2 < NST) {
            const int nbuf = (st + 2) % 3;
            STAGE_LOAD(st + 2, nbuf);
        }
        CP_COMMIT();

        const int tap = st >> 1, half = st & 1;
        const int row = t + tap - HW;
        if (row >= 0 && row < Sn) {
            const int buf_off = (st % 3) * STAGE4;
            #pragma unroll 1
            for (int i = 0; i < 2; i++) {
                const int e4 = qh * 64 + i * 32 + lane;    // [0,128) within half
                const int qg = half * 128 + e4;            // [0,256) within row
                float4 xv[4];
                #pragma unroll
                for (int j = 0; j < 4; j++)
                    xv[j] = x4[((size_t)(bg * 4 + j) * Sn + row) * En4 + qg];
                #pragma unroll
                for (int v = 0; v < Wn; v++) {
                    const float4 w4 = s_w[buf_off + v * 128 + e4];
                    #pragma unroll
                    for (int j = 0; j < 4; j++) {
                        acc[j][v] = fmaf(xv[j].x, w4.x, acc[j][v]);
                        acc[j][v] = fmaf(xv[j].y, w4.y, acc[j][v]);
                        acc[j][v] = fmaf(xv[j].z, w4.z, acc[j][v]);
                        acc[j][v] = fmaf(xv[j].w, w4.w, acc[j][v]);
                    }
                }
            }
        }
    }

    // Warp tree-reduce 28 partials, publish per q-quarter group.
    #pragma unroll
    for (int j = 0; j < 4; j++) {
        #pragma unroll
        for (int v = 0; v < Wn; v++) {
            float s = acc[j][v];
            s += __shfl_xor_sync(0xffffffffu, s, 16);
            s += __shfl_xor_sync(0xffffffffu, s, 8);
            s += __shfl_xor_sync(0xffffffffu, s, 4);
            s += __shfl_xor_sync(0xffffffffu, s, 2);
            s += __shfl_xor_sync(0xffffffffu, s, 1);
            if (lane == 0) s_part[qh][bg * 4 + j][v] = s;
        }
    }
    __syncthreads();

    if (tid < Bn * Wn) {
        const int b = tid / Wn, v = tid % Wn;
        const float l = s_part[0][b][v] + s_part[1][b][v] + bias[t * Wn + v];
        s_g[b][v] = 1.0f / (1.0f + __expf(-l));
    }
    __syncthreads();

    // Stage 3: out[b,t,:] = tanh(sum_tap g[b][tap] * x[b, t+tap-3, :])
    const int q = tid;
    #pragma unroll 2
    for (int b = 0; b < Bn; b++) {
        float o0 = 0.f, o1 = 0.f, o2 = 0.f, o3 = 0.f;
        #pragma unroll
        for (int tap = 0; tap < Wn; tap++) {
            const int row = t + tap - HW;
            if (row >= 0 && row < Sn) {
                const float g = s_g[b][tap];
                const float4 xv = x4[((size_t)b * Sn + row) * En4 + q];
                o0 = fmaf(g, xv.x, o0);
                o1 = fmaf(g, xv.y, o1);
                o2 = fmaf(g, xv.z, o2);
                o3 = fmaf(g, xv.w, o3);
            }
        }
        float4 r;
        r.x = fast_tanh(o0);
        r.y = fast_tanh(o1);
        r.z = fast_tanh(o2);
        r.w = fast_tanh(o3);
        ((float4*)out)[((size_t)b * Sn + t) * En4 + q] = r;
    }
}

extern "C" void kernel_launch(void* const* d_in, const int* in_sizes, int n_in,
                              void* d_out, int out_size)
{
    const float* x      = (const float*)d_in[0];
    const float* weight = (const float*)d_in[1];
    const float* bias   = (const float*)d_in[2];
    float* out          = (float*)d_out;

    cudaFuncSetAttribute(soft_reordering_fused,
                         cudaFuncAttributeMaxDynamicSharedMemorySize, SMEM_BYTES);
    soft_reordering_fused<<<Sn, 256, SMEM_BYTES>>>(x, weight, bias, out);
}